// round 10
// baseline (speedup 1.0000x reference)
#include <cuda_runtime.h>
#include <math.h>
#include <float.h>

// ---------------- problem constants ----------------
#define NN        8192      // nodes
#define EE        65536     // edges
#define M1        16
#define DD        4
#define M2        16
#define M2H       48        // 3*M2
#define HS        64        // M2*D
#define NH        4         // attention heads
#define EDGE_DIM  32
#define EHID      64
#define NI        96        // M2H*P
#define NJ        32        // M1*K
#define KROWS     2080      // EHID*NJ + NJ (bias rows appended)
#define NTILES    65        // KROWS / NJ
#define EB        64        // edges per CTA in main kernel
#define NT        128       // threads per CTA

// dup-packed weight tile layout: per (tile, j): 8 og-chunks of stride 28 words,
// each chunk = 12 dup-pairs (24 floats) + 4 pad. Row = 224 words, tile = 32*224.
#define OGSTRIDE  28
#define WROW      224       // 8 * OGSTRIDE
#define WTILE_F   (NJ * WROW)   // 7168 floats per tile (28 KB)

// ---------------- device scratch (no allocation allowed) ----------------
__device__ __align__(16) float g_W2pp[NTILES * WTILE_F]; // dup-packed weights
__device__ float g_scores[EE * NH];
__device__ __align__(16) float g_v[EE * HS];
__device__ float g_nmax[NN * NH];
__device__ float g_nsum[NN * NH];
__device__ float g_agg[NN * HS];

// ---------------- packed fp32x2 helpers (SASS FFMA2/FMUL2 path) ----------------
typedef unsigned long long u64;

__device__ __forceinline__ u64 pack2(float a, float b) {
    u64 r; asm("mov.b64 %0, {%1,%2};" : "=l"(r) : "f"(a), "f"(b)); return r;
}
__device__ __forceinline__ void unpack2(u64 v, float& a, float& b) {
    asm("mov.b64 {%0,%1}, %2;" : "=f"(a), "=f"(b) : "l"(v));
}
__device__ __forceinline__ u64 fma2(u64 a, u64 b, u64 c) {
    u64 d; asm("fma.rn.f32x2 %0, %1, %2, %3;" : "=l"(d) : "l"(a), "l"(b), "l"(c));
    return d;
}
__device__ __forceinline__ u64 mul2(u64 a, u64 b) {
    u64 d; asm("mul.rn.f32x2 %0, %1, %2;" : "=l"(d) : "l"(a), "l"(b));
    return d;
}

// ---------------- helpers ----------------
__device__ __forceinline__ void atomicMaxF(float* addr, float val) {
    int old = __float_as_int(*addr);
    while (__int_as_float(old) < val) {
        int assumed = old;
        old = atomicCAS(reinterpret_cast<int*>(addr), assumed, __float_as_int(val));
        if (old == assumed) break;
    }
}

// ---------------- kernel 0a: build dup-packed weight tiles ----------------
// source rw_w2 is [c][i*32+j]; rows 2048..2079 hold rw_bias2 (h := 1 rows).
// dst: g_W2pp[((ct*32+j)*224) + og*28 + p*2 + {0,1}] = W[row= ct*32+j][i= og*12+p]
__global__ void k_prep(const float* __restrict__ w2, const float* __restrict__ b2) {
    int idx = blockIdx.x * blockDim.x + threadIdx.x;
    if (idx >= KROWS * NI) return;
    int row = idx / NI;
    int i   = idx - row * NI;
    float v;
    if (row < EHID * NJ) {
        int c = row >> 5, j = row & 31;
        v = w2[c * (NI * NJ) + i * NJ + j];
    } else {
        int j = row - EHID * NJ;
        v = b2[i * NJ + j];
    }
    int og = i / 12, p = i - og * 12;
    int off = row * WROW + og * OGSTRIDE + p * 2;
    g_W2pp[off]     = v;
    g_W2pp[off + 1] = v;
}

// ---------------- kernel 0b: reset reductions ----------------
__global__ void k_init() {
    int idx = blockIdx.x * blockDim.x + threadIdx.x;
    if (idx < NN * HS) g_agg[idx] = 0.f;
    if (idx < NN * NH) { g_nmax[idx] = -FLT_MAX; g_nsum[idx] = 0.f; }
}

// ---------------- kernel 1: per-edge heavy compute ----------------
// per CTA: 64 edges, 128 threads. h (edge MLP), t (f_src.basis1), then
// acc[e,i] = sum_{c,j} h[c]*t[j]*W2[cj,i] via edge-paired f32x2 FMAs:
// gt_pair = mul2(h_pair, t_pair); acc_pair[i] = fma2(gt_pair, {w_i,w_i}, .)
// then conv = t2 . basis2, scores (k.q), v; atomicMax for softmax.
__global__ void __launch_bounds__(NT, 4) k_edge(
    const float* __restrict__ ef, const float* __restrict__ f,
    const float* __restrict__ b1, const float* __restrict__ b2,
    const int*   __restrict__ src_idx, const int* __restrict__ dst_idx,
    const float* __restrict__ w1, const float* __restrict__ bias1)
{
    extern __shared__ float smem[];
    float* h_s  = smem;                        // [64][EB]  16 KB
    float* t_s  = smem + EHID * EB;            // [32][EB]   8 KB
    float* w_s  = smem + (EHID + NJ) * EB;     // WTILE_F   28 KB
    float* t2_s = smem;                        // [96][EB] overlays h_s+t_s (24 KB)

    const int tid = threadIdx.x;
    const int el  = tid & 63;                  // edge-lane 0..63
    const int half= tid >> 6;                  // 0,1
    const int e   = blockIdx.x * EB + el;

    // --- load W1 into w_s front (consumed by h-MLP before tile 0 overwrites) ---
    for (int idx = tid; idx < EDGE_DIM * EHID; idx += NT) w_s[idx] = w1[idx];

    // --- t[j] = sum_d f[src,m,d] * basis1[e,d,k],  j = m*2+k  (m split by half) ---
    {
        const int s = src_idx[e];
        float b1r[8];
        #pragma unroll
        for (int z = 0; z < 8; ++z) b1r[z] = b1[e * 8 + z];   // [d][k]
        const float4* frow = reinterpret_cast<const float4*>(f) + s * M1;
        #pragma unroll
        for (int mm = 0; mm < 8; ++mm) {
            int m = half * 8 + mm;
            float4 fv = frow[m];
            t_s[(2 * m + 0) * EB + el] = fv.x * b1r[0] + fv.y * b1r[2] + fv.z * b1r[4] + fv.w * b1r[6];
            t_s[(2 * m + 1) * EB + el] = fv.x * b1r[1] + fv.y * b1r[3] + fv.z * b1r[5] + fv.w * b1r[7];
        }
    }
    __syncthreads();   // W1 ready

    // --- h[c] = relu(ef . W1 + bias1), c split by half ---
    {
        float efr[EDGE_DIM];
        #pragma unroll
        for (int x = 0; x < EDGE_DIM; ++x) efr[x] = ef[e * EDGE_DIM + x];
        #pragma unroll 4
        for (int cc = 0; cc < 32; ++cc) {
            int c = half * 32 + cc;
            float s = bias1[c];
            #pragma unroll
            for (int x = 0; x < EDGE_DIM; ++x) s = fmaf(efr[x], w_s[x * EHID + c], s);
            h_s[c * EB + el] = fmaxf(s, 0.f);
        }
    }

    // --- main loop over 65 tiles (last = bias rows, h := 1) ---
    // thread tile: 4 edges (2 pairs) x 12 outputs
    const int eg = tid >> 3;        // 0..15 (edge group, 4 edges each)
    const int og = tid & 7;         // 0..7  (output group, 12 i each)
    const int ebase = eg * 4;

    u64 acc2[2][12];
    #pragma unroll
    for (int rp = 0; rp < 2; ++rp)
        #pragma unroll
        for (int p = 0; p < 12; ++p) acc2[rp][p] = 0ULL;

    const u64 ones2 = pack2(1.f, 1.f);

    for (int ct = 0; ct < NTILES; ++ct) {
        __syncthreads();   // prev tile consumed (ct=0: h_s/t_s ready, W1 reads done)
        {
            const float4* gsrc = reinterpret_cast<const float4*>(g_W2pp + ct * WTILE_F);
            float4* sdst = reinterpret_cast<float4*>(w_s);
            #pragma unroll
            for (int q = 0; q < WTILE_F / (4 * NT); ++q)   // 14 float4 per thread
                sdst[q * NT + tid] = gsrc[q * NT + tid];
        }
        __syncthreads();

        u64 hv2[2];
        if (ct < EHID) {
            ulonglong2 hp = *reinterpret_cast<const ulonglong2*>(&h_s[ct * EB + ebase]);
            hv2[0] = hp.x; hv2[1] = hp.y;
        } else {
            hv2[0] = ones2; hv2[1] = ones2;
        }

        #pragma unroll 8
        for (int j = 0; j < NJ; ++j) {
            ulonglong2 tp = *reinterpret_cast<const ulonglong2*>(&t_s[j * EB + ebase]);
            u64 gt0 = mul2(hv2[0], tp.x);
            u64 gt1 = mul2(hv2[1], tp.y);

            const ulonglong2* wrow =
                reinterpret_cast<const ulonglong2*>(&w_s[j * WROW + og * OGSTRIDE]);
            #pragma unroll
            for (int q = 0; q < 6; ++q) {          // 12 dup-pairs as 6 LDS.128
                ulonglong2 wq = wrow[q];
                acc2[0][2*q]   = fma2(gt0, wq.x, acc2[0][2*q]);
                acc2[1][2*q]   = fma2(gt1, wq.x, acc2[1][2*q]);
                acc2[0][2*q+1] = fma2(gt0, wq.y, acc2[0][2*q+1]);
                acc2[1][2*q+1] = fma2(gt1, wq.y, acc2[1][2*q+1]);
            }
        }
    }

    __syncthreads();
    // --- stash t2 = acc into shared, [i][e] layout ---
    #pragma unroll
    for (int rp = 0; rp < 2; ++rp)
        #pragma unroll
        for (int p = 0; p < 12; ++p) {
            float a, b;
            unpack2(acc2[rp][p], a, b);
            t2_s[(og * 12 + p) * EB + ebase + 2 * rp + 0] = a;
            t2_s[(og * 12 + p) * EB + ebase + 2 * rp + 1] = b;
        }
    __syncthreads();

    // --- epilogue: conv = t2 . basis2 ; scores ; v  (o-range split by half) ---
    {
        float b2r[8];
        #pragma unroll
        for (int z = 0; z < 8; ++z) b2r[z] = b2[e * 8 + z];   // [p][d]

        float sc0 = 0.f, sc1 = 0.f;     // heads half*2, half*2+1
        #pragma unroll
        for (int o8 = 0; o8 < 8; ++o8) {
            int o = half * 8 + o8;
            float a0 = t2_s[(2 * o) * EB + el],      a1 = t2_s[(2 * o + 1) * EB + el];
            float q0 = t2_s[(2 * o + 32) * EB + el], q1 = t2_s[(2 * o + 33) * EB + el];
            float dot = 0.f;
            #pragma unroll
            for (int d = 0; d < 4; ++d) {
                float kk = a0 * b2r[d] + a1 * b2r[4 + d];
                float qq = q0 * b2r[d] + q1 * b2r[4 + d];
                dot = fmaf(kk, qq, dot);
            }
            if (o8 < 4) sc0 += dot; else sc1 += dot;
        }
        #pragma unroll
        for (int o8 = 0; o8 < 8; ++o8) {
            int o = half * 8 + o8;
            float a0 = t2_s[(2 * o + 64) * EB + el], a1 = t2_s[(2 * o + 65) * EB + el];
            float4 vv;
            vv.x = a0 * b2r[0] + a1 * b2r[4];
            vv.y = a0 * b2r[1] + a1 * b2r[5];
            vv.z = a0 * b2r[2] + a1 * b2r[6];
            vv.w = a0 * b2r[3] + a1 * b2r[7];
            reinterpret_cast<float4*>(g_v)[e * 16 + o] = vv;
        }
        const int dn = dst_idx[e];
        #pragma unroll
        for (int hq = 0; hq < 2; ++hq) {
            int hh = half * 2 + hq;
            float s = (hq == 0 ? sc0 : sc1) * 0.125f;   // TEMP = HS^-0.5
            s = (s > 0.f) ? s : 0.2f * s;               // leaky_relu(., 0.2)
            g_scores[e * NH + hh] = s;
            atomicMaxF(&g_nmax[dn * NH + hh], s);
        }
    }
}

// ---------------- kernel 2: softmax denominator ----------------
__global__ void k_sum(const int* __restrict__ dst_idx) {
    int idx = blockIdx.x * blockDim.x + threadIdx.x;
    if (idx >= EE * NH) return;
    int e = idx >> 2, hh = idx & 3;
    int dn = dst_idx[e];
    float ex = expf(g_scores[idx] - g_nmax[dn * NH + hh]);
    atomicAdd(&g_nsum[dn * NH + hh], ex);
}

// ---------------- kernel 3: weighted aggregation (copy_e_sum) ----------------
__global__ void k_agg(const int* __restrict__ dst_idx) {
    int idx = blockIdx.x * blockDim.x + threadIdx.x;
    if (idx >= EE * HS) return;
    int e = idx >> 6, x = idx & 63, hh = x >> 4;
    int dn = dst_idx[e];
    float w = expf(g_scores[e * NH + hh] - g_nmax[dn * NH + hh]) / g_nsum[dn * NH + hh];
    atomicAdd(&g_agg[dn * HS + x], w * g_v[idx]);
}

// ---------------- kernel 4: per-irrep equivariant projection ----------------
__global__ void k_proj(const float* __restrict__ pw, const float* __restrict__ pb,
                       float* __restrict__ out) {
    int idx = blockIdx.x * blockDim.x + threadIdx.x;
    if (idx >= NN * HS) return;
    int n  = idx >> 6;
    int m2 = (idx >> 2) & 15;
    int d  = idx & 3;
    int blk = (d == 0) ? 0 : 1;                // IRREP_IDX = [0,1,1,1]
    const float* pwr = pw + (blk * M2 + m2) * M2;
    float s = (d == 0) ? pb[m2] : 0.f;
    #pragma unroll
    for (int m = 0; m < M2; ++m) s = fmaf(pwr[m], g_agg[n * HS + m * 4 + d], s);
    out[idx] = s;
}

// ---------------- launch ----------------
extern "C" void kernel_launch(void* const* d_in, const int* in_sizes, int n_in,
                              void* d_out, int out_size) {
    // setup_inputs() dict order:
    const float* ef    = (const float*)d_in[0];   // edge_feats (E,32)
    const float* f     = (const float*)d_in[1];   // f (N,16,4)
    const float* b1    = (const float*)d_in[2];   // basis1 (E,4,2)
    const float* b2    = (const float*)d_in[3];   // basis2 (E,2,4)
    const int*   src   = (const int*)  d_in[4];   // src_idx (E)
    const int*   dst   = (const int*)  d_in[5];   // dst_idx (E)
    const float* w1    = (const float*)d_in[6];   // rw_w1 (32,64)
    const float* bias1 = (const float*)d_in[7];   // rw_bias1 (64)
    const float* w2    = (const float*)d_in[8];   // rw_w2 (64,3072)
    const float* bias2 = (const float*)d_in[9];   // rw_bias2 (3072)
    const float* pw    = (const float*)d_in[10];  // proj_w (32,16)
    const float* pb    = (const float*)d_in[11];  // proj_b (16,1)
    float* out = (float*)d_out;

    (void)in_sizes; (void)n_in; (void)out_size;

    const int SMEM = (EHID + NJ) * EB * 4 + WTILE_F * 4;   // 53248 B
    cudaFuncSetAttribute(k_edge, cudaFuncAttributeMaxDynamicSharedMemorySize, SMEM);

    k_prep<<<(KROWS * NI + 255) / 256, 256>>>(w2, bias2);
    k_init<<<(NN * HS + 255) / 256, 256>>>();
    k_edge<<<EE / EB, NT, SMEM>>>(ef, f, b1, b2, src, dst, w1, bias1);
    k_sum<<<(EE * NH + 255) / 256, 256>>>(dst);
    k_agg<<<(EE * HS + 255) / 256, 256>>>(dst);
    k_proj<<<(NN * HS + 255) / 256, 256>>>(pw, pb, out);
}

// round 12
// speedup vs baseline: 3.4443x; 3.4443x over previous
#include <cuda_runtime.h>
#include <cuda_bf16.h>
#include <math.h>
#include <float.h>
#include <stdint.h>

// ---------------- problem constants ----------------
#define NN        8192
#define EE        65536
#define M1        16
#define M2        16
#define HS        64        // M2*D
#define NH        4
#define EDGE_DIM  32
#define EHID      64
#define NI        96        // output dim (GEMM N)
#define NJ        32        // M1*K
#define KTOT      2112      // 2080 real K rows padded to 33*64
#define NSLAB     33        // 64-k slabs
#define EB        128       // edges per CTA (GEMM M)
#define NT        128       // threads per CTA (4 warps)

// ---------------- device scratch (no allocation allowed) ----------------
// W pre-packed in mma.m16n8k16 B-fragment layout:
// g_Wf[((s*4+ks)*12+nf)*32+lane] = {hi_reg0, hi_reg1, lo_reg0, lo_reg1}
__device__ __align__(16) uint4 g_Wf[NSLAB * 4 * 12 * 32];
__device__ float g_scores[EE * NH];
__device__ __align__(16) float g_v[EE * HS];
__device__ float g_nmax[NN * NH];
__device__ float g_nsum[NN * NH];
__device__ float g_agg[NN * HS];

// ---------------- smem layout (bytes) ----------------
// h_s:  66 x 128 f32                    [0, 33792)
// Ghi:  128 rows x 144B (64 bf16 + pad) [33792, 52224)
// Glo:  128 rows x 144B                 [52224, 70656)
// Wslab: 4ks x 12nf x 32lane x 16B      [70656, 95232)
// t2_s: 96 x 128 f32 overlays h_s+G     [0, 49152)
#define SO_G    33792
#define SO_GLO  52224
#define GROWB   144
#define SO_W    70656
#define SMEM_BYTES 95232

// ---------------- ptx helpers ----------------
__device__ __forceinline__ void cp_async16(uint32_t saddr, const void* gsrc) {
    asm volatile("cp.async.cg.shared.global [%0], [%1], 16;" :: "r"(saddr), "l"(gsrc));
}
#define CP_COMMIT() asm volatile("cp.async.commit_group;" ::: "memory")
#define CP_WAIT0()  asm volatile("cp.async.wait_group 0;" ::: "memory")

__device__ __forceinline__ void ldsm4(uint32_t* r, uint32_t saddr) {
    asm volatile("ldmatrix.sync.aligned.m8n8.x4.shared.b16 {%0,%1,%2,%3}, [%4];"
        : "=r"(r[0]), "=r"(r[1]), "=r"(r[2]), "=r"(r[3]) : "r"(saddr));
}
__device__ __forceinline__ void hmma(float* c, const uint32_t* a, uint32_t b0, uint32_t b1) {
    asm volatile(
        "mma.sync.aligned.m16n8k16.row.col.f32.bf16.bf16.f32 "
        "{%0,%1,%2,%3}, {%4,%5,%6,%7}, {%8,%9}, {%0,%1,%2,%3};"
        : "+f"(c[0]), "+f"(c[1]), "+f"(c[2]), "+f"(c[3])
        : "r"(a[0]), "r"(a[1]), "r"(a[2]), "r"(a[3]), "r"(b0), "r"(b1));
}
// pack two f32 -> bf16x2, v0 in lower 16 bits (first PTX src = upper half)
__device__ __forceinline__ uint32_t pack_bf16x2(float v0, float v1) {
    uint32_t r;
    asm("cvt.rn.bf16x2.f32 %0, %1, %2;" : "=r"(r) : "f"(v1), "f"(v0));
    return r;
}

__device__ __forceinline__ void atomicMaxF(float* addr, float val) {
    int old = __float_as_int(*addr);
    while (__int_as_float(old) < val) {
        int assumed = old;
        old = atomicCAS(reinterpret_cast<int*>(addr), assumed, __float_as_int(val));
        if (old == assumed) break;
    }
}

// ---------------- kernel 0a: pre-split W into B-fragment layout ----------------
// W(k, n): k<2048 -> w2[(k>>5)*3072 + n*32 + (k&31)]; k<2080 -> bias2[n*32 + k-2048]; else 0
__device__ __forceinline__ float fetchW(const float* w2, const float* b2, int k, int n) {
    if (k < 2048) return w2[(k >> 5) * (NI * NJ) + n * NJ + (k & 31)];
    if (k < 2080) return b2[n * NJ + (k - 2048)];
    return 0.f;
}
__global__ void k_prepB(const float* __restrict__ w2, const float* __restrict__ b2) {
    int idx = blockIdx.x * blockDim.x + threadIdx.x;
    if (idx >= NSLAB * 4 * 12 * 32) return;
    int lane = idx & 31;
    int t    = idx >> 5;
    int nf   = t % 12;
    int t2   = t / 12;
    int ks   = t2 & 3;
    int s    = t2 >> 2;
    int ksg  = s * 4 + ks;
    int n    = nf * 8 + lane / 4;
    int kb   = ksg * 16 + (lane & 3) * 2;

    float w[4];                           // b0,b1 (k, k+1), b2,b3 (k+8, k+9)
    w[0] = fetchW(w2, b2, kb,     n);
    w[1] = fetchW(w2, b2, kb + 1, n);
    w[2] = fetchW(w2, b2, kb + 8, n);
    w[3] = fetchW(w2, b2, kb + 9, n);

    float hi[4], lo[4];
    #pragma unroll
    for (int q = 0; q < 4; ++q) {
        hi[q] = __bfloat162float(__float2bfloat16(w[q]));
        lo[q] = w[q] - hi[q];
    }
    g_Wf[idx] = make_uint4(pack_bf16x2(hi[0], hi[1]), pack_bf16x2(hi[2], hi[3]),
                           pack_bf16x2(lo[0], lo[1]), pack_bf16x2(lo[2], lo[3]));
}

// ---------------- kernel 0b: reset reductions ----------------
__global__ void k_init() {
    int idx = blockIdx.x * blockDim.x + threadIdx.x;
    if (idx < NN * HS) g_agg[idx] = 0.f;
    if (idx < NN * NH) { g_nmax[idx] = -FLT_MAX; g_nsum[idx] = 0.f; }
}

// ---------------- kernel 1: per-edge compute via bf16x3 mma.sync ----------------
__global__ void __launch_bounds__(NT, 2) k_edge(
    const float* __restrict__ ef, const float* __restrict__ f,
    const float* __restrict__ b1, const float* __restrict__ b2,
    const int*   __restrict__ src_idx, const int* __restrict__ dst_idx,
    const float* __restrict__ w1, const float* __restrict__ bias1)
{
    extern __shared__ __align__(16) char smem[];
    const uint32_t sb = (uint32_t)__cvta_generic_to_shared(smem);
    float* h_s  = reinterpret_cast<float*>(smem);
    float* t2_s = reinterpret_cast<float*>(smem);

    const int tid  = threadIdx.x;
    const int wid  = tid >> 5;
    const int lane = tid & 31;
    const int e    = blockIdx.x * EB + tid;

    // --- stage W1 in the W-slab area (consumed before slab 0 cp.async) ---
    float* w1_s = reinterpret_cast<float*>(smem + SO_W);
    for (int idx = tid; idx < EDGE_DIM * EHID; idx += NT) w1_s[idx] = w1[idx];

    // --- t[j] in registers (thread = edge) ---
    float t_r[NJ];
    {
        const int s = src_idx[e];
        float b1r[8];
        #pragma unroll
        for (int z = 0; z < 8; ++z) b1r[z] = b1[e * 8 + z];   // [d][k]
        const float4* frow = reinterpret_cast<const float4*>(f) + s * M1;
        #pragma unroll
        for (int m = 0; m < M1; ++m) {
            float4 fv = frow[m];
            t_r[2*m+0] = fv.x*b1r[0] + fv.y*b1r[2] + fv.z*b1r[4] + fv.w*b1r[6];
            t_r[2*m+1] = fv.x*b1r[1] + fv.y*b1r[3] + fv.z*b1r[5] + fv.w*b1r[7];
        }
    }
    __syncthreads();   // W1 visible

    // --- h[c] = relu(ef . W1 + bias1) -> h_s[c][e]; row 64 = 1 (bias), 65 = 0 (pad) ---
    {
        float efr[EDGE_DIM];
        #pragma unroll
        for (int x = 0; x < EDGE_DIM; ++x) efr[x] = ef[e * EDGE_DIM + x];
        #pragma unroll 4
        for (int c = 0; c < EHID; ++c) {
            float s = bias1[c];
            #pragma unroll
            for (int x = 0; x < EDGE_DIM; ++x) s = fmaf(efr[x], w1_s[x * EHID + c], s);
            h_s[c * EB + tid] = fmaxf(s, 0.f);
        }
        h_s[64 * EB + tid] = 1.f;
        h_s[65 * EB + tid] = 0.f;
    }
    // h_s rows are thread-private (written & read by thread tid only) -> no sync needed.

    // --- main loop: 33 slabs of 64 K ---
    // warp quadrants: wid&1 -> n half (6 nf), wid>>1 -> m half (4 m-frags = 64 edges)
    const int nbase = (wid & 1) * 6;
    const int ebq   = (wid >> 1) * 64;

    float acc[4][6][4];
    #pragma unroll
    for (int mf = 0; mf < 4; ++mf)
        #pragma unroll
        for (int nf = 0; nf < 6; ++nf)
            #pragma unroll
            for (int q = 0; q < 4; ++q) acc[mf][nf][q] = 0.f;

    char* growH = smem + SO_G   + tid * GROWB;
    char* growL = smem + SO_GLO + tid * GROWB;

    for (int s = 0; s < NSLAB; ++s) {
        __syncthreads();   // prior slab's MMA reads of G/W complete (also W1 h-MLP at s=0)

        // prefetch W slab s (24 KB): 12 x 16B per thread
        {
            const uint4* wsrc = g_Wf + s * 1536;
            #pragma unroll
            for (int q = 0; q < 12; ++q)
                cp_async16(sb + SO_W + (q * NT + tid) * 16, wsrc + q * NT + tid);
            CP_COMMIT();
        }

        // build this edge's G row (64 k): k = 64s + cl*32 + j; G = h[2s+cl] * t[j]
        float hv0 = h_s[(2 * s)     * EB + tid];
        float hv1 = h_s[(2 * s + 1) * EB + tid];
        #pragma unroll
        for (int cl = 0; cl < 2; ++cl) {
            float hv = cl ? hv1 : hv0;
            #pragma unroll
            for (int g = 0; g < 4; ++g) {           // 8 values = 16B per chunk
                float v[8];
                #pragma unroll
                for (int q = 0; q < 8; ++q) v[q] = hv * t_r[g * 8 + q];
                uint32_t H[4], L[4];
                #pragma unroll
                for (int p = 0; p < 4; ++p) {
                    H[p] = pack_bf16x2(v[2*p], v[2*p+1]);
                    float f0 = __uint_as_float(H[p] << 16);
                    float f1 = __uint_as_float(H[p] & 0xffff0000u);
                    L[p] = pack_bf16x2(v[2*p] - f0, v[2*p+1] - f1);
                }
                *reinterpret_cast<uint4*>(growH + cl * 64 + g * 16) =
                    make_uint4(H[0], H[1], H[2], H[3]);
                *reinterpret_cast<uint4*>(growL + cl * 64 + g * 16) =
                    make_uint4(L[0], L[1], L[2], L[3]);
            }
        }

        CP_WAIT0();
        __syncthreads();   // G + W slab visible to all warps

        // MMA: 4 k-steps x (4 m-frags x 6 n-frags x 3 split terms)
        const int rl = lane & 15;                 // ldmatrix row within 16
        const int ch = (lane >> 4) * 16;          // column-half byte offset
        #pragma unroll
        for (int ks = 0; ks < 4; ++ks) {
            uint32_t Ah[4][4], Al[4][4];
            #pragma unroll
            for (int mf = 0; mf < 4; ++mf) {
                uint32_t ra = sb + SO_G + (ebq + mf * 16 + rl) * GROWB + ch + ks * 32;
                ldsm4(Ah[mf], ra);
                ldsm4(Al[mf], ra + (SO_GLO - SO_G));
            }
            #pragma unroll
            for (int nf = 0; nf < 6; ++nf) {
                uint4 B = *reinterpret_cast<const uint4*>(
                    smem + SO_W + ((ks * 12 + nbase + nf) * 32 + lane) * 16);
                #pragma unroll
                for (int mf = 0; mf < 4; ++mf) {
                    hmma(acc[mf][nf], Ah[mf], B.x, B.y);   // hi*hi
                    hmma(acc[mf][nf], Ah[mf], B.z, B.w);   // hi*lo
                    hmma(acc[mf][nf], Al[mf], B.x, B.y);   // lo*hi
                }
            }
        }
    }

    __syncthreads();
    // --- store accumulators -> t2_s [i][e] (overlays h_s + G) ---
    #pragma unroll
    for (int mf = 0; mf < 4; ++mf) {
        int e0 = ebq + mf * 16 + lane / 4;
        #pragma unroll
        for (int nf = 0; nf < 6; ++nf) {
            int i0 = (nbase + nf) * 8 + (lane & 3) * 2;
            t2_s[(i0    ) * EB + e0    ] = acc[mf][nf][0];
            t2_s[(i0 + 1) * EB + e0    ] = acc[mf][nf][1];
            t2_s[(i0    ) * EB + e0 + 8] = acc[mf][nf][2];
            t2_s[(i0 + 1) * EB + e0 + 8] = acc[mf][nf][3];
        }
    }
    __syncthreads();

    // --- epilogue: conv = t2 . basis2 ; scores ; v  (thread = edge) ---
    {
        float b2r[8];
        #pragma unroll
        for (int z = 0; z < 8; ++z) b2r[z] = b2[e * 8 + z];   // [p][d]

        float sc[4] = {0.f, 0.f, 0.f, 0.f};
        #pragma unroll
        for (int o = 0; o < 16; ++o) {
            float a0 = t2_s[(2 * o) * EB + tid],      a1 = t2_s[(2 * o + 1) * EB + tid];
            float q0 = t2_s[(2 * o + 32) * EB + tid], q1 = t2_s[(2 * o + 33) * EB + tid];
            float dot = 0.f;
            #pragma unroll
            for (int d = 0; d < 4; ++d) {
                float kk = a0 * b2r[d] + a1 * b2r[4 + d];
                float qq = q0 * b2r[d] + q1 * b2r[4 + d];
                dot = fmaf(kk, qq, dot);
            }
            sc[o >> 2] += dot;
        }
        #pragma unroll
        for (int o = 0; o < 16; ++o) {
            float a0 = t2_s[(2 * o + 64) * EB + tid], a1 = t2_s[(2 * o + 65) * EB + tid];
            float4 vv;
            vv.x = a0 * b2r[0] + a1 * b2r[4];
            vv.y = a0 * b2r[1] + a1 * b2r[5];
            vv.z = a0 * b2r[2] + a1 * b2r[6];
            vv.w = a0 * b2r[3] + a1 * b2r[7];
            reinterpret_cast<float4*>(g_v)[e * 16 + o] = vv;
        }
        const int dn = dst_idx[e];
        #pragma unroll
        for (int hh = 0; hh < NH; ++hh) {
            float s = sc[hh] * 0.125f;                 // TEMP = HS^-0.5
            s = (s > 0.f) ? s : 0.2f * s;              // leaky_relu(., 0.2)
            g_scores[e * NH + hh] = s;
            atomicMaxF(&g_nmax[dn * NH + hh], s);
        }
    }
}

// ---------------- kernel 2: softmax denominator ----------------
__global__ void k_sum(const int* __restrict__ dst_idx) {
    int idx = blockIdx.x * blockDim.x + threadIdx.x;
    if (idx >= EE * NH) return;
    int e = idx >> 2, hh = idx & 3;
    int dn = dst_idx[e];
    float ex = expf(g_scores[idx] - g_nmax[dn * NH + hh]);
    atomicAdd(&g_nsum[dn * NH + hh], ex);
}

// ---------------- kernel 3: weighted aggregation (copy_e_sum) ----------------
__global__ void k_agg(const int* __restrict__ dst_idx) {
    int idx = blockIdx.x * blockDim.x + threadIdx.x;
    if (idx >= EE * HS) return;
    int e = idx >> 6, x = idx & 63, hh = x >> 4;
    int dn = dst_idx[e];
    float w = expf(g_scores[e * NH + hh] - g_nmax[dn * NH + hh]) / g_nsum[dn * NH + hh];
    atomicAdd(&g_agg[dn * HS + x], w * g_v[idx]);
}

// ---------------- kernel 4: per-irrep equivariant projection ----------------
__global__ void k_proj(const float* __restrict__ pw, const float* __restrict__ pb,
                       float* __restrict__ out) {
    int idx = blockIdx.x * blockDim.x + threadIdx.x;
    if (idx >= NN * HS) return;
    int n  = idx >> 6;
    int m2 = (idx >> 2) & 15;
    int d  = idx & 3;
    int blk = (d == 0) ? 0 : 1;                // IRREP_IDX = [0,1,1,1]
    const float* pwr = pw + (blk * M2 + m2) * M2;
    float s = (d == 0) ? pb[m2] : 0.f;
    #pragma unroll
    for (int m = 0; m < M2; ++m) s = fmaf(pwr[m], g_agg[n * HS + m * 4 + d], s);
    out[idx] = s;
}

// ---------------- launch ----------------
extern "C" void kernel_launch(void* const* d_in, const int* in_sizes, int n_in,
                              void* d_out, int out_size) {
    const float* ef    = (const float*)d_in[0];   // edge_feats (E,32)
    const float* f     = (const float*)d_in[1];   // f (N,16,4)
    const float* b1    = (const float*)d_in[2];   // basis1 (E,4,2)
    const float* b2    = (const float*)d_in[3];   // basis2 (E,2,4)
    const int*   src   = (const int*)  d_in[4];   // src_idx (E)
    const int*   dst   = (const int*)  d_in[5];   // dst_idx (E)
    const float* w1    = (const float*)d_in[6];   // rw_w1 (32,64)
    const float* bias1 = (const float*)d_in[7];   // rw_bias1 (64)
    const float* w2    = (const float*)d_in[8];   // rw_w2 (64,3072)
    const float* bias2 = (const float*)d_in[9];   // rw_bias2 (3072)
    const float* pw    = (const float*)d_in[10];  // proj_w (32,16)
    const float* pb    = (const float*)d_in[11];  // proj_b (16,1)
    float* out = (float*)d_out;

    (void)in_sizes; (void)n_in; (void)out_size;

    cudaFuncSetAttribute(k_edge, cudaFuncAttributeMaxDynamicSharedMemorySize, SMEM_BYTES);

    k_prepB<<<(NSLAB * 4 * 12 * 32 + 255) / 256, 256>>>(w2, bias2);
    k_init<<<(NN * HS + 255) / 256, 256>>>();
    k_edge<<<EE / EB, NT, SMEM_BYTES>>>(ef, f, b1, b2, src, dst, w1, bias1);
    k_sum<<<(EE * NH + 255) / 256, 256>>>(dst);
    k_agg<<<(EE * HS + 255) / 256, 256>>>(dst);
    k_proj<<<(NN * HS + 255) / 256, 256>>>(pw, pb, out);
}

// round 14
// speedup vs baseline: 3.4662x; 1.0063x over previous
#include <cuda_runtime.h>
#include <cuda_bf16.h>
#include <math.h>
#include <float.h>
#include <stdint.h>

// ---------------- problem constants ----------------
#define NN        8192
#define EE        65536
#define M1        16
#define M2        16
#define HS        64        // M2*D
#define NH        4
#define EDGE_DIM  32
#define EHID      64
#define NI        96        // output dim (GEMM N)
#define NJ        32        // M1*K
#define NSLAB     33        // 64-k slabs (2080 real + 32 zero/bias rows)
#define EB        128       // edges per CTA (GEMM M)
#define NT        128       // threads per CTA (4 warps)

// ---------------- device scratch ----------------
// W pre-packed in mma.m16n8k16 B-fragment layout:
// g_Wf[((s*4+ks)*12+nf)*32+lane] = {hi_reg0, hi_reg1, lo_reg0, lo_reg1}
__device__ __align__(16) uint4 g_Wf[NSLAB * 4 * 12 * 32];
__device__ float g_h[66 * EE];          // h[c][e]; rows 64=1, 65=0 (bias/pad)
__device__ float g_scores[EE * NH];
__device__ __align__(16) float g_v[EE * HS];
__device__ float g_nmax[NN * NH];
__device__ float g_nsum[NN * NH];
__device__ float g_agg[NN * HS];

// ---------------- smem layout (bytes) ----------------
// G buf b (b=0,1): hi at b*32768, lo at b*32768+16384  (128 rows x 128B, XOR-swizzled)
// W buf b: 65536 + b*24576   (4ks x 12nf x 32lane x 16B)
// t2_s (96 x 128 f32 = 48KB) overlays G buffers after the loop.
#define SO_GBUF(b)  ((b) * 32768)
#define GLO_OFF     16384
#define SO_W(b)     (65536 + (b) * 24576)
#define SMEM_BYTES  114688

// ---------------- ptx helpers ----------------
__device__ __forceinline__ void cp_async16(uint32_t saddr, const void* gsrc) {
    asm volatile("cp.async.cg.shared.global [%0], [%1], 16;" :: "r"(saddr), "l"(gsrc));
}
#define CP_COMMIT() asm volatile("cp.async.commit_group;" ::: "memory")
#define CP_WAIT0()  asm volatile("cp.async.wait_group 0;" ::: "memory")

__device__ __forceinline__ void ldsm4(uint32_t* r, uint32_t saddr) {
    asm volatile("ldmatrix.sync.aligned.m8n8.x4.shared.b16 {%0,%1,%2,%3}, [%4];"
        : "=r"(r[0]), "=r"(r[1]), "=r"(r[2]), "=r"(r[3]) : "r"(saddr));
}
__device__ __forceinline__ void hmma(float* c, const uint32_t* a, uint32_t b0, uint32_t b1) {
    asm volatile(
        "mma.sync.aligned.m16n8k16.row.col.f32.bf16.bf16.f32 "
        "{%0,%1,%2,%3}, {%4,%5,%6,%7}, {%8,%9}, {%0,%1,%2,%3};"
        : "+f"(c[0]), "+f"(c[1]), "+f"(c[2]), "+f"(c[3])
        : "r"(a[0]), "r"(a[1]), "r"(a[2]), "r"(a[3]), "r"(b0), "r"(b1));
}
// pack two f32 -> bf16x2, v0 in lower 16 bits
__device__ __forceinline__ uint32_t pack_bf16x2(float v0, float v1) {
    uint32_t r;
    asm("cvt.rn.bf16x2.f32 %0, %1, %2;" : "=r"(r) : "f"(v1), "f"(v0));
    return r;
}

__device__ __forceinline__ void atomicMaxF(float* addr, float val) {
    int old = __float_as_int(*addr);
    while (__int_as_float(old) < val) {
        int assumed = old;
        old = atomicCAS(reinterpret_cast<int*>(addr), assumed, __float_as_int(val));
        if (old == assumed) break;
    }
}

// ---------------- kernel 0a: pre-split W into B-fragment layout ----------------
__device__ __forceinline__ float fetchW(const float* w2, const float* b2, int k, int n) {
    if (k < 2048) return w2[(k >> 5) * (NI * NJ) + n * NJ + (k & 31)];
    if (k < 2080) return b2[n * NJ + (k - 2048)];
    return 0.f;
}
__global__ void k_prepB(const float* __restrict__ w2, const float* __restrict__ b2) {
    int idx = blockIdx.x * blockDim.x + threadIdx.x;
    if (idx >= NSLAB * 4 * 12 * 32) return;
    int lane = idx & 31;
    int t    = idx >> 5;
    int nf   = t % 12;
    int t2   = t / 12;
    int ks   = t2 & 3;
    int s    = t2 >> 2;
    int ksg  = s * 4 + ks;
    int n    = nf * 8 + lane / 4;
    int kb   = ksg * 16 + (lane & 3) * 2;

    float w[4];
    w[0] = fetchW(w2, b2, kb,     n);
    w[1] = fetchW(w2, b2, kb + 1, n);
    w[2] = fetchW(w2, b2, kb + 8, n);
    w[3] = fetchW(w2, b2, kb + 9, n);

    float hi[4], lo[4];
    #pragma unroll
    for (int q = 0; q < 4; ++q) {
        hi[q] = __bfloat162float(__float2bfloat16(w[q]));
        lo[q] = w[q] - hi[q];
    }
    g_Wf[idx] = make_uint4(pack_bf16x2(hi[0], hi[1]), pack_bf16x2(hi[2], hi[3]),
                           pack_bf16x2(lo[0], lo[1]), pack_bf16x2(lo[2], lo[3]));
}

// ---------------- kernel 0b: edge-MLP hidden h[c][e] ----------------
__global__ void __launch_bounds__(256) k_hid(
    const float* __restrict__ ef, const float* __restrict__ w1,
    const float* __restrict__ bias1)
{
    __shared__ float w1_s[EDGE_DIM * EHID];
    __shared__ float b1_s[EHID];
    int tid = threadIdx.x;
    for (int i = tid; i < EDGE_DIM * EHID; i += 256) w1_s[i] = w1[i];
    if (tid < EHID) b1_s[tid] = bias1[tid];
    __syncthreads();

    int e = blockIdx.x * 256 + tid;
    float efr[EDGE_DIM];
    #pragma unroll
    for (int x = 0; x < EDGE_DIM; ++x) efr[x] = ef[e * EDGE_DIM + x];
    #pragma unroll 4
    for (int c = 0; c < EHID; ++c) {
        float s = b1_s[c];
        #pragma unroll
        for (int x = 0; x < EDGE_DIM; ++x) s = fmaf(efr[x], w1_s[x * EHID + c], s);
        g_h[c * EE + e] = fmaxf(s, 0.f);
    }
    g_h[64 * EE + e] = 1.f;   // bias rows (first 32 k of slab 32)
    g_h[65 * EE + e] = 0.f;   // zero pad  (last 32 k of slab 32)
}

// ---------------- kernel 0c: reset reductions ----------------
__global__ void k_init() {
    int idx = blockIdx.x * blockDim.x + threadIdx.x;
    if (idx < NN * HS) g_agg[idx] = 0.f;
    if (idx < NN * NH) { g_nmax[idx] = -FLT_MAX; g_nsum[idx] = 0.f; }
}

// ---------------- kernel 1: pipelined bf16x3 mma.sync ----------------
__global__ void __launch_bounds__(NT, 2) k_edge(
    const float* __restrict__ f,
    const float* __restrict__ b1, const float* __restrict__ b2,
    const int*   __restrict__ src_idx, const int* __restrict__ dst_idx)
{
    extern __shared__ __align__(16) char smem[];
    const uint32_t sb = (uint32_t)__cvta_generic_to_shared(smem);
    float* t2_s = reinterpret_cast<float*>(smem);

    const int tid  = threadIdx.x;
    const int wid  = tid >> 5;
    const int lane = tid & 31;
    const int e    = blockIdx.x * EB + tid;

    // --- t[j] in registers (thread = edge) ---
    float t_r[NJ];
    {
        const int s = src_idx[e];
        float b1r[8];
        #pragma unroll
        for (int z = 0; z < 8; ++z) b1r[z] = b1[e * 8 + z];   // [d][k]
        const float4* frow = reinterpret_cast<const float4*>(f) + s * M1;
        #pragma unroll
        for (int m = 0; m < M1; ++m) {
            float4 fv = frow[m];
            t_r[2*m+0] = fv.x*b1r[0] + fv.y*b1r[2] + fv.z*b1r[4] + fv.w*b1r[6];
            t_r[2*m+1] = fv.x*b1r[1] + fv.y*b1r[3] + fv.z*b1r[5] + fv.w*b1r[7];
        }
    }

    // build helper: write this edge's G row of slab into buf b
    // row tid, chunk c (16B, 8 bf16 = k 8c..8c+7) at tid*128 + ((c ^ (tid&7)) * 16)
    char* growbase = smem;   // + SO_GBUF(b) [+ GLO_OFF]
    const int rowoff = tid * 128;
    const int rsw    = tid & 7;

    auto build_g = [&](int buf, float ha, float hb) {
        char* gh = growbase + SO_GBUF(buf) + rowoff;
        char* gl = gh + GLO_OFF;
        #pragma unroll
        for (int cl = 0; cl < 2; ++cl) {
            float hv = cl ? hb : ha;
            #pragma unroll
            for (int g = 0; g < 4; ++g) {
                float v[8];
                #pragma unroll
                for (int q = 0; q < 8; ++q) v[q] = hv * t_r[g * 8 + q];
                uint32_t H[4], L[4];
                #pragma unroll
                for (int p = 0; p < 4; ++p) {
                    H[p] = pack_bf16x2(v[2*p], v[2*p+1]);
                    float f0 = __uint_as_float(H[p] << 16);
                    float f1 = __uint_as_float(H[p] & 0xffff0000u);
                    L[p] = pack_bf16x2(v[2*p] - f0, v[2*p+1] - f1);
                }
                int sw = (((cl << 2) | g) ^ rsw) << 4;
                *reinterpret_cast<uint4*>(gh + sw) = make_uint4(H[0], H[1], H[2], H[3]);
                *reinterpret_cast<uint4*>(gl + sw) = make_uint4(L[0], L[1], L[2], L[3]);
            }
        }
    };

    // prologue: load h(0), h(1); build G(0); prefetch W(0)
    float h0a = g_h[0 * EE + e], h0b = g_h[1 * EE + e];
    float hna = g_h[2 * EE + e], hnb = g_h[3 * EE + e];

    build_g(0, h0a, h0b);
    {   // prefetch W(0) into W buf 0
        const uint4* wsrc = g_Wf;
        #pragma unroll
        for (int q = 0; q < 12; ++q)
            cp_async16(sb + SO_W(0) + (q * NT + tid) * 16, wsrc + q * NT + tid);
        CP_COMMIT();
    }

    // warp quadrants
    const int nbase = (wid & 1) * 6;
    const int ebq   = (wid >> 1) * 64;

    float acc[4][6][4];
    #pragma unroll
    for (int mf = 0; mf < 4; ++mf)
        #pragma unroll
        for (int nf = 0; nf < 6; ++nf)
            #pragma unroll
            for (int q = 0; q < 4; ++q) acc[mf][nf][q] = 0.f;

    const int rl    = lane & 15;
    const int chbit = lane >> 4;

    for (int s = 0; s < NSLAB; ++s) {
        CP_WAIT0();          // W(s) landed
        __syncthreads();     // G(s) built & visible; MMA(s-1) reads complete

        // prefetch W(s+1) into alt buf (safe: MMA(s-1) reads of that buf are done)
        if (s + 1 < NSLAB) {
            const uint4* wsrc = g_Wf + (s + 1) * 1536;
            #pragma unroll
            for (int q = 0; q < 12; ++q)
                cp_async16(sb + SO_W((s + 1) & 1) + (q * NT + tid) * 16,
                           wsrc + q * NT + tid);
            CP_COMMIT();
        }

        // build G(s+1) into alt buf; stage h(s+2)
        if (s + 1 < NSLAB) {
            float ha = hna, hb = hnb;
            if (s + 2 < NSLAB) {
                hna = g_h[(2 * s + 4) * EE + e];
                hnb = g_h[(2 * s + 5) * EE + e];
            }
            build_g((s + 1) & 1, ha, hb);
        }

        // MMA(s): reads G buf s&1, W buf s&1
        const uint32_t gbase = sb + SO_GBUF(s & 1);
        const uint32_t wbase = sb + SO_W(s & 1);
        #pragma unroll
        for (int ks = 0; ks < 4; ++ks) {
            uint32_t Ah[4][4], Al[4][4];
            #pragma unroll
            for (int mf = 0; mf < 4; ++mf) {
                int r  = ebq + mf * 16 + rl;
                int sw = (((ks << 1) | chbit) ^ (r & 7)) << 4;
                uint32_t ra = gbase + r * 128 + sw;
                ldsm4(Ah[mf], ra);
                ldsm4(Al[mf], ra + GLO_OFF);
            }
            #pragma unroll
            for (int nf = 0; nf < 6; ++nf) {
                uint4 B = *reinterpret_cast<const uint4*>(
                    smem + (wbase - sb) + ((ks * 12 + nbase + nf) * 32 + lane) * 16);
                #pragma unroll
                for (int mf = 0; mf < 4; ++mf) {
                    hmma(acc[mf][nf], Ah[mf], B.x, B.y);   // hi*hi
                    hmma(acc[mf][nf], Ah[mf], B.z, B.w);   // hi*lo
                    hmma(acc[mf][nf], Al[mf], B.x, B.y);   // lo*hi
                }
            }
        }
    }

    __syncthreads();   // all LDSM of final slab done; G bufs reusable as t2_s
    #pragma unroll
    for (int mf = 0; mf < 4; ++mf) {
        int e0 = ebq + mf * 16 + lane / 4;
        #pragma unroll
        for (int nf = 0; nf < 6; ++nf) {
            int i0 = (nbase + nf) * 8 + (lane & 3) * 2;
            t2_s[(i0    ) * EB + e0    ] = acc[mf][nf][0];
            t2_s[(i0 + 1) * EB + e0    ] = acc[mf][nf][1];
            t2_s[(i0    ) * EB + e0 + 8] = acc[mf][nf][2];
            t2_s[(i0 + 1) * EB + e0 + 8] = acc[mf][nf][3];
        }
    }
    __syncthreads();

    // --- epilogue: conv = t2 . basis2 ; scores ; v  (thread = edge) ---
    {
        float b2r[8];
        #pragma unroll
        for (int z = 0; z < 8; ++z) b2r[z] = b2[e * 8 + z];   // [p][d]

        float sc[4] = {0.f, 0.f, 0.f, 0.f};
        #pragma unroll
        for (int o = 0; o < 16; ++o) {
            float a0 = t2_s[(2 * o) * EB + tid],      a1 = t2_s[(2 * o + 1) * EB + tid];
            float q0 = t2_s[(2 * o + 32) * EB + tid], q1 = t2_s[(2 * o + 33) * EB + tid];
            float dot = 0.f;
            #pragma unroll
            for (int d = 0; d < 4; ++d) {
                float kk = a0 * b2r[d] + a1 * b2r[4 + d];
                float qq = q0 * b2r[d] + q1 * b2r[4 + d];
                dot = fmaf(kk, qq, dot);
            }
            sc[o >> 2] += dot;
        }
        #pragma unroll
        for (int o = 0; o < 16; ++o) {
            float a0 = t2_s[(2 * o + 64) * EB + tid], a1 = t2_s[(2 * o + 65) * EB + tid];
            float4 vv;
            vv.x = a0 * b2r[0] + a1 * b2r[4];
            vv.y = a0 * b2r[1] + a1 * b2r[5];
            vv.z = a0 * b2r[2] + a1 * b2r[6];
            vv.w = a0 * b2r[3] + a1 * b2r[7];
            reinterpret_cast<float4*>(g_v)[e * 16 + o] = vv;
        }
        const int dn = dst_idx[e];
        #pragma unroll
        for (int hh = 0; hh < NH; ++hh) {
            float s = sc[hh] * 0.125f;                 // TEMP = HS^-0.5
            s = (s > 0.f) ? s : 0.2f * s;              // leaky_relu(., 0.2)
            g_scores[e * NH + hh] = s;
            atomicMaxF(&g_nmax[dn * NH + hh], s);
        }
    }
}

// ---------------- kernel 2: softmax denominator ----------------
__global__ void k_sum(const int* __restrict__ dst_idx) {
    int idx = blockIdx.x * blockDim.x + threadIdx.x;
    if (idx >= EE * NH) return;
    int e = idx >> 2, hh = idx & 3;
    int dn = dst_idx[e];
    float ex = expf(g_scores[idx] - g_nmax[dn * NH + hh]);
    atomicAdd(&g_nsum[dn * NH + hh], ex);
}

// ---------------- kernel 3: weighted aggregation (copy_e_sum) ----------------
__global__ void k_agg(const int* __restrict__ dst_idx) {
    int idx = blockIdx.x * blockDim.x + threadIdx.x;
    if (idx >= EE * HS) return;
    int e = idx >> 6, x = idx & 63, hh = x >> 4;
    int dn = dst_idx[e];
    float w = expf(g_scores[e * NH + hh] - g_nmax[dn * NH + hh]) / g_nsum[dn * NH + hh];
    atomicAdd(&g_agg[dn * HS + x], w * g_v[idx]);
}

// ---------------- kernel 4: per-irrep equivariant projection ----------------
__global__ void k_proj(const float* __restrict__ pw, const float* __restrict__ pb,
                       float* __restrict__ out) {
    int idx = blockIdx.x * blockDim.x + threadIdx.x;
    if (idx >= NN * HS) return;
    int n  = idx >> 6;
    int m2 = (idx >> 2) & 15;
    int d  = idx & 3;
    int blk = (d == 0) ? 0 : 1;                // IRREP_IDX = [0,1,1,1]
    const float* pwr = pw + (blk * M2 + m2) * M2;
    float s = (d == 0) ? pb[m2] : 0.f;
    #pragma unroll
    for (int m = 0; m < M2; ++m) s = fmaf(pwr[m], g_agg[n * HS + m * 4 + d], s);
    out[idx] = s;
}

// ---------------- launch ----------------
extern "C" void kernel_launch(void* const* d_in, const int* in_sizes, int n_in,
                              void* d_out, int out_size) {
    const float* ef    = (const float*)d_in[0];   // edge_feats (E,32)
    const float* f     = (const float*)d_in[1];   // f (N,16,4)
    const float* b1    = (const float*)d_in[2];   // basis1 (E,4,2)
    const float* b2    = (const float*)d_in[3];   // basis2 (E,2,4)
    const int*   src   = (const int*)  d_in[4];   // src_idx (E)
    const int*   dst   = (const int*)  d_in[5];   // dst_idx (E)
    const float* w1    = (const float*)d_in[6];   // rw_w1 (32,64)
    const float* bias1 = (const float*)d_in[7];   // rw_bias1 (64)
    const float* w2    = (const float*)d_in[8];   // rw_w2 (64,3072)
    const float* bias2 = (const float*)d_in[9];   // rw_bias2 (3072)
    const float* pw    = (const float*)d_in[10];  // proj_w (32,16)
    const float* pb    = (const float*)d_in[11];  // proj_b (16,1)
    float* out = (float*)d_out;

    (void)in_sizes; (void)n_in; (void)out_size;

    cudaFuncSetAttribute(k_edge, cudaFuncAttributeMaxDynamicSharedMemorySize, SMEM_BYTES);

    k_prepB<<<(NSLAB * 4 * 12 * 32 + 255) / 256, 256>>>(w2, bias2);
    k_hid<<<EE / 256, 256>>>(ef, w1, bias1);
    k_init<<<(NN * HS + 255) / 256, 256>>>();
    k_edge<<<EE / EB, NT, SMEM_BYTES>>>(f, b1, b2, src, dst);
    k_sum<<<(EE * NH + 255) / 256, 256>>>(dst);
    k_agg<<<(EE * HS + 255) / 256, 256>>>(dst);
    k_proj<<<(NN * HS + 255) / 256, 256>>>(pw, pb, out);
}